// round 1
// baseline (speedup 1.0000x reference)
#include <cuda_runtime.h>

#define KSZ   5
#define CIN   3
#define BATCH 2
#define HH    48
#define KN    16
#define OH    44
#define PP    1936            // OH*OH
#define IMG_ELEMS (CIN*HH*HH) // 6912

#define TILE 128

// ---------------------------------------------------------------------------
// Sigma kernel: sigma[b,kn,p,q] = (sum_f xm[b,p,f]*xm[b,q,f]) * softplus(w_sigma[kn])
// Gram matrix computed directly from the SMEM-resident image via patch indexing.
// Thread block: 256 threads (16x16). Tile 128x128 of (p,q). 8x8 microtile/thread.
// q mapping per thread: q = q0 + tx + s*16  -> lane-stride-1 LDS (conflict-free),
// coalesced 64B stores per half-warp.
// ---------------------------------------------------------------------------
__global__ __launch_bounds__(256, 2)
void vdp_sigma_kernel(const float* __restrict__ mu_in,
                      const float* __restrict__ w_sigma,
                      float* __restrict__ sigma)
{
    __shared__ float img[IMG_ELEMS];
    __shared__ float sp[KN];

    const int tid = threadIdx.x;
    const int tx  = tid & 15;
    const int ty  = tid >> 4;
    const int b   = blockIdx.z;
    const int p0  = blockIdx.y * TILE;
    const int q0  = blockIdx.x * TILE;

    // Load full per-batch image into SMEM (27648 B)
    const float* src = mu_in + b * IMG_ELEMS;
    #pragma unroll
    for (int i = tid; i < IMG_ELEMS; i += 256) img[i] = src[i];
    if (tid < KN) {
        sp[tid] = log1pf(expf(w_sigma[tid]));
    }
    __syncthreads();

    // Patch base addresses for this thread's 8 p-rows and 8 q-cols
    int basep[8], baseq[8];
    bool pv[8], qv[8];
    #pragma unroll
    for (int r = 0; r < 8; r++) {
        int p = p0 + ty * 8 + r;
        pv[r] = (p < PP);
        int pc = pv[r] ? p : 0;
        int ph = pc / OH, pw = pc - ph * OH;
        basep[r] = ph * HH + pw;
    }
    #pragma unroll
    for (int s = 0; s < 8; s++) {
        int q = q0 + tx + s * 16;
        qv[s] = (q < PP);
        int qc = qv[s] ? q : 0;
        int qh = qc / OH, qw = qc - qh * OH;
        baseq[s] = qh * HH + qw;
    }

    float acc[8][8];
    #pragma unroll
    for (int r = 0; r < 8; r++)
        #pragma unroll
        for (int s = 0; s < 8; s++) acc[r][s] = 0.0f;

    // Gram accumulation over f = (c, i, j): 75 taps
    for (int c = 0; c < CIN; c++) {
        for (int i = 0; i < KSZ; i++) {
            int off0 = c * (HH * HH) + i * HH;
            #pragma unroll
            for (int j = 0; j < KSZ; j++) {
                int off = off0 + j;
                float av[8], bv[8];
                #pragma unroll
                for (int r = 0; r < 8; r++) av[r] = img[basep[r] + off];
                #pragma unroll
                for (int s = 0; s < 8; s++) bv[s] = img[baseq[s] + off];
                #pragma unroll
                for (int r = 0; r < 8; r++)
                    #pragma unroll
                    for (int s = 0; s < 8; s++)
                        acc[r][s] = fmaf(av[r], bv[s], acc[r][s]);
            }
        }
    }

    // Store: 16 scaled planes. For fixed (r,kn,s) lanes write consecutive floats.
    const size_t planeStride = (size_t)PP * PP;
    #pragma unroll
    for (int r = 0; r < 8; r++) {
        if (!pv[r]) continue;
        int p = p0 + ty * 8 + r;
        size_t rowbase = ((size_t)b * KN) * planeStride + (size_t)p * PP + (size_t)(q0 + tx);
        for (int kn = 0; kn < KN; kn++) {
            float sc = sp[kn];
            float* outp = sigma + rowbase + (size_t)kn * planeStride;
            #pragma unroll
            for (int s = 0; s < 8; s++) {
                if (qv[s]) outp[s * 16] = acc[r][s] * sc;
            }
        }
    }
}

// ---------------------------------------------------------------------------
// Mean path: plain valid conv, one thread per output element (62K outputs).
// ---------------------------------------------------------------------------
__global__ __launch_bounds__(256)
void vdp_mu_kernel(const float* __restrict__ mu_in,
                   const float* __restrict__ w_mu,
                   float* __restrict__ mu_out)
{
    int idx = blockIdx.x * blockDim.x + threadIdx.x;
    const int total = BATCH * KN * OH * OH;
    if (idx >= total) return;

    int ox = idx % OH;
    int oy = (idx / OH) % OH;
    int kn = (idx / (OH * OH)) % KN;
    int b  = idx / (OH * OH * KN);

    const float* img = mu_in + b * IMG_ELEMS;
    const float* w   = w_mu + kn * (CIN * KSZ * KSZ);

    float acc = 0.0f;
    #pragma unroll
    for (int c = 0; c < CIN; c++) {
        #pragma unroll
        for (int i = 0; i < KSZ; i++) {
            #pragma unroll
            for (int j = 0; j < KSZ; j++) {
                acc = fmaf(__ldg(&img[c * HH * HH + (oy + i) * HH + ox + j]),
                           __ldg(&w[c * KSZ * KSZ + i * KSZ + j]), acc);
            }
        }
    }
    mu_out[idx] = acc;
}

extern "C" void kernel_launch(void* const* d_in, const int* in_sizes, int n_in,
                              void* d_out, int out_size)
{
    const float* mu_in   = (const float*)d_in[0];
    const float* w_mu    = (const float*)d_in[1];
    const float* w_sigma = (const float*)d_in[2];

    float* out    = (float*)d_out;
    float* mu_out = out;                                  // [2,16,44,44]
    float* sigma  = out + (size_t)BATCH * KN * OH * OH;   // [2,16,1936,1936]

    const int mu_total = BATCH * KN * OH * OH;
    vdp_mu_kernel<<<(mu_total + 255) / 256, 256>>>(mu_in, w_mu, mu_out);

    dim3 grid((PP + TILE - 1) / TILE, (PP + TILE - 1) / TILE, BATCH);  // 16,16,2
    vdp_sigma_kernel<<<grid, 256>>>(mu_in, w_sigma, sigma);
}

// round 2
// speedup vs baseline: 1.1546x; 1.1546x over previous
#include <cuda_runtime.h>

#define KSZ   5
#define CIN   3
#define BATCH 2
#define HH    48
#define KN    16
#define OH    44
#define PP    1936            // OH*OH
#define IMG_ELEMS (CIN*HH*HH) // 6912

#define TILE 128

typedef unsigned long long u64;

__device__ __forceinline__ u64 pack2(float lo, float hi) {
    u64 r; asm("mov.b64 %0, {%1,%2};" : "=l"(r) : "f"(lo), "f"(hi)); return r;
}
__device__ __forceinline__ void fma2(u64 &d, u64 a, u64 b) {
    asm("fma.rn.f32x2 %0, %1, %2, %0;" : "+l"(d) : "l"(a), "l"(b));
}
__device__ __forceinline__ float2 unpack2(u64 v) {
    float2 f; asm("mov.b64 {%0,%1}, %2;" : "=f"(f.x), "=f"(f.y) : "l"(v)); return f;
}

// ---------------------------------------------------------------------------
// sigma[b,kn,p,q] = (sum_f xm[b,p,f]*xm[b,q,f]) * softplus(w_sigma[kn])
// 256 threads (16x16), 128x128 tile, 8x8 microtile.
// Compute layout: p = p0 + ty*8 + r,  q = q0 + tx + s*16 (conflict-free LDS).
// Accumulate in f32x2 pairs (s packed 2-wide).
// Epilogue: transpose 32-row chunks through padded SMEM, then STG.128 x16 planes.
// ---------------------------------------------------------------------------
__global__ __launch_bounds__(256, 2)
void vdp_sigma_kernel(const float* __restrict__ mu_in,
                      const float* __restrict__ w_sigma,
                      float* __restrict__ sigma)
{
    __shared__ float img[IMG_ELEMS];
    __shared__ float spv[KN];
    __shared__ float tile[32][132];   // padded row stride: conflict-free vec4 reads

    const int tid = threadIdx.x;
    const int tx  = tid & 15;
    const int ty  = tid >> 4;
    const int b   = blockIdx.z;
    const int p0  = blockIdx.y * TILE;
    const int q0  = blockIdx.x * TILE;

    // Load per-batch image (27.6 KB) + softplus scales
    const float* src = mu_in + b * IMG_ELEMS;
    for (int i = tid; i < IMG_ELEMS; i += 256) img[i] = src[i];
    if (tid < KN) spv[tid] = log1pf(expf(w_sigma[tid]));
    __syncthreads();

    // Patch base addresses
    int basep[8], baseq[8];
    #pragma unroll
    for (int r = 0; r < 8; r++) {
        int p = p0 + ty * 8 + r;
        int pc = (p < PP) ? p : 0;
        int ph = pc / OH, pw = pc - ph * OH;
        basep[r] = ph * HH + pw;
    }
    #pragma unroll
    for (int s = 0; s < 8; s++) {
        int q = q0 + tx + s * 16;
        int qc = (q < PP) ? q : 0;
        int qh = qc / OH, qw = qc - qh * OH;
        baseq[s] = qh * HH + qw;
    }

    u64 acc[8][4];
    #pragma unroll
    for (int r = 0; r < 8; r++)
        #pragma unroll
        for (int h = 0; h < 4; h++) acc[r][h] = 0ULL;

    // Gram accumulation: 3 channels x 25 unrolled taps
    #pragma unroll 1
    for (int c = 0; c < CIN; c++) {
        int bp[8], bq[8];
        const int coff = c * (HH * HH);
        #pragma unroll
        for (int r = 0; r < 8; r++) bp[r] = basep[r] + coff;
        #pragma unroll
        for (int s = 0; s < 8; s++) bq[s] = baseq[s] + coff;

        #pragma unroll
        for (int i = 0; i < KSZ; i++) {
            #pragma unroll
            for (int j = 0; j < KSZ; j++) {
                const int off = i * HH + j;
                float av[8], bv[8];
                #pragma unroll
                for (int r = 0; r < 8; r++) av[r] = img[bp[r] + off];
                #pragma unroll
                for (int s = 0; s < 8; s++) bv[s] = img[bq[s] + off];

                u64 avp[8], bvp[4];
                #pragma unroll
                for (int r = 0; r < 8; r++) avp[r] = pack2(av[r], av[r]);
                #pragma unroll
                for (int h = 0; h < 4; h++) bvp[h] = pack2(bv[2*h], bv[2*h+1]);

                #pragma unroll
                for (int r = 0; r < 8; r++)
                    #pragma unroll
                    for (int h = 0; h < 4; h++)
                        fma2(acc[r][h], avp[r], bvp[h]);
            }
        }
    }

    // ---------------- Epilogue: chunked transpose + vectorized stores -------
    const size_t planeStride = (size_t)PP * PP;
    const int qoff   = (tid & 7) * 16;         // 16 consecutive q per thread
    const int plread = tid >> 3;               // 0..31 row within chunk

    float sc[KN];
    #pragma unroll
    for (int kn = 0; kn < KN; kn++) sc[kn] = spv[kn];

    #pragma unroll 1
    for (int cc = 0; cc < 4; cc++) {
        __syncthreads();
        if ((ty >> 2) == cc) {
            int pl = (ty & 3) * 8;
            #pragma unroll
            for (int r = 0; r < 8; r++) {
                #pragma unroll
                for (int h = 0; h < 4; h++) {
                    float2 f = unpack2(acc[r][h]);
                    tile[pl + r][tx + 32*h]      = f.x;
                    tile[pl + r][tx + 32*h + 16] = f.y;
                }
            }
        }
        __syncthreads();

        int p = p0 + cc * 32 + plread;
        if (p >= PP) continue;

        float4 v[4];
        #pragma unroll
        for (int k = 0; k < 4; k++)
            v[k] = *(const float4*)&tile[plread][qoff + 4*k];

        bool qv[4];
        #pragma unroll
        for (int k = 0; k < 4; k++) qv[k] = (q0 + qoff + 4*k) < PP;

        float* base = sigma + (size_t)b * KN * planeStride
                            + (size_t)p * PP + (size_t)(q0 + qoff);
        #pragma unroll
        for (int kn = 0; kn < KN; kn++) {
            float s = sc[kn];
            float* o = base + (size_t)kn * planeStride;
            #pragma unroll
            for (int k = 0; k < 4; k++) {
                if (qv[k]) {
                    float4 w;
                    w.x = v[k].x * s; w.y = v[k].y * s;
                    w.z = v[k].z * s; w.w = v[k].w * s;
                    *(float4*)(o + 4*k) = w;
                }
            }
        }
    }
}

// ---------------------------------------------------------------------------
// Mean path: plain valid conv, one thread per output element.
// ---------------------------------------------------------------------------
__global__ __launch_bounds__(256)
void vdp_mu_kernel(const float* __restrict__ mu_in,
                   const float* __restrict__ w_mu,
                   float* __restrict__ mu_out)
{
    int idx = blockIdx.x * blockDim.x + threadIdx.x;
    const int total = BATCH * KN * OH * OH;
    if (idx >= total) return;

    int ox = idx % OH;
    int oy = (idx / OH) % OH;
    int kn = (idx / (OH * OH)) % KN;
    int b  = idx / (OH * OH * KN);

    const float* im = mu_in + b * IMG_ELEMS;
    const float* w  = w_mu + kn * (CIN * KSZ * KSZ);

    float acc = 0.0f;
    #pragma unroll
    for (int c = 0; c < CIN; c++)
        #pragma unroll
        for (int i = 0; i < KSZ; i++)
            #pragma unroll
            for (int j = 0; j < KSZ; j++)
                acc = fmaf(__ldg(&im[c * HH * HH + (oy + i) * HH + ox + j]),
                           __ldg(&w[c * KSZ * KSZ + i * KSZ + j]), acc);
    mu_out[idx] = acc;
}

extern "C" void kernel_launch(void* const* d_in, const int* in_sizes, int n_in,
                              void* d_out, int out_size)
{
    const float* mu_in   = (const float*)d_in[0];
    const float* w_mu    = (const float*)d_in[1];
    const float* w_sigma = (const float*)d_in[2];

    float* out    = (float*)d_out;
    float* mu_out = out;
    float* sigma  = out + (size_t)BATCH * KN * OH * OH;

    const int mu_total = BATCH * KN * OH * OH;
    vdp_mu_kernel<<<(mu_total + 255) / 256, 256>>>(mu_in, w_mu, mu_out);

    dim3 grid((PP + TILE - 1) / TILE, (PP + TILE - 1) / TILE, BATCH);
    vdp_sigma_kernel<<<grid, 256>>>(mu_in, w_sigma, sigma);
}